// round 11
// baseline (speedup 1.0000x reference)
#include <cuda_runtime.h>
#include <cuda_bf16.h>
#include <cstdint>

#define CC 128
#define MAX_N 100000
#define MAX_E 1600000
#define SCAN_T 512
#define NCHUNK 4

__device__ float g_deg[MAX_N];           // dinv
__device__ float g_t[(size_t)MAX_N * CC];
__device__ float g_h[(size_t)MAX_N * CC];
__device__ float g_t2[(size_t)MAX_N * CC];
__device__ float g_h2[(size_t)MAX_N * CC];
__device__ float g_z1[(size_t)MAX_N * CC];
__device__ float g_z2[(size_t)MAX_N * CC];
__device__ int g_cnt[MAX_N];
__device__ int g_off[MAX_N];
__device__ int g_cur[MAX_N];
__device__ int g_bsum[256];
__device__ int g_csr[MAX_E];
__device__ __nv_bfloat16 g_wt[4][2][128 * 128];

// ================= helpers =================

__device__ __forceinline__ uint32_t smem_u32(const void* p) {
    uint32_t a;
    asm("{ .reg .u64 t; cvta.to.shared.u64 t, %1; cvt.u32.u64 %0, t; }" : "=r"(a) : "l"(p));
    return a;
}

#define SWZ128(o) ((o) ^ (((o) >> 3) & 0x70))

__device__ __forceinline__ void ldsm_x4(uint32_t addr, uint32_t* r) {
    asm volatile("ldmatrix.sync.aligned.m8n8.x4.shared.b16 {%0,%1,%2,%3}, [%4];"
                 : "=r"(r[0]), "=r"(r[1]), "=r"(r[2]), "=r"(r[3]) : "r"(addr));
}

__device__ __forceinline__ void mma_bf16(float* d, const uint32_t* a, uint32_t b0, uint32_t b1) {
    asm volatile("mma.sync.aligned.m16n8k16.row.col.f32.bf16.bf16.f32 "
                 "{%0,%1,%2,%3}, {%4,%5,%6,%7}, {%8,%9}, {%0,%1,%2,%3};"
                 : "+f"(d[0]), "+f"(d[1]), "+f"(d[2]), "+f"(d[3])
                 : "r"(a[0]), "r"(a[1]), "r"(a[2]), "r"(a[3]), "r"(b0), "r"(b1));
}

__device__ __forceinline__ uint32_t pack_bf16(__nv_bfloat16 lo, __nv_bfloat16 hi) {
    return ((uint32_t)__bfloat16_as_ushort(hi) << 16) | (uint32_t)__bfloat16_as_ushort(lo);
}

__device__ __forceinline__ void split_store(char* smem, uint32_t offH, uint32_t offL, float4 v) {
    __nv_bfloat16 hx = __float2bfloat16_rn(v.x);
    __nv_bfloat16 hy = __float2bfloat16_rn(v.y);
    __nv_bfloat16 hz = __float2bfloat16_rn(v.z);
    __nv_bfloat16 hw = __float2bfloat16_rn(v.w);
    __nv_bfloat16 lx = __float2bfloat16_rn(v.x - __bfloat162float(hx));
    __nv_bfloat16 ly = __float2bfloat16_rn(v.y - __bfloat162float(hy));
    __nv_bfloat16 lz = __float2bfloat16_rn(v.z - __bfloat162float(hz));
    __nv_bfloat16 lw = __float2bfloat16_rn(v.w - __bfloat162float(hw));
    *reinterpret_cast<uint2*>(smem + offH) = make_uint2(pack_bf16(hx, hy), pack_bf16(hz, hw));
    *reinterpret_cast<uint2*>(smem + offL) = make_uint2(pack_bf16(lx, ly), pack_bf16(lz, lw));
}

// ================= CSR build =================

__global__ void zero_cnt_kernel(int* cnt, int N) {
    int i = blockIdx.x * blockDim.x + threadIdx.x;
    if (i < N) cnt[i] = 0;
}

__global__ void hist_kernel(int* cnt, const int* __restrict__ col, int E) {
    int i = blockIdx.x * blockDim.x + threadIdx.x;
    if (i < E) atomicAdd(&cnt[col[i]], 1);
}

__global__ void scan1_kernel(const int* __restrict__ cnt, int* excl, int* bsum,
                             float* dinv, int N) {
    __shared__ int s[SCAN_T];
    int i = blockIdx.x * SCAN_T + threadIdx.x;
    int v = (i < N) ? cnt[i] : 0;
    if (i < N) dinv[i] = rsqrtf((float)v + 1.0f);
    s[threadIdx.x] = v;
    __syncthreads();
#pragma unroll
    for (int d = 1; d < SCAN_T; d <<= 1) {
        int t = (threadIdx.x >= d) ? s[threadIdx.x - d] : 0;
        __syncthreads();
        s[threadIdx.x] += t;
        __syncthreads();
    }
    if (i < N) excl[i] = s[threadIdx.x] - v;
    if (threadIdx.x == SCAN_T - 1) bsum[blockIdx.x] = s[SCAN_T - 1];
}

__global__ void scan2_kernel(int* bsum, int nb) {
    __shared__ int s[256];
    int v = (threadIdx.x < nb) ? bsum[threadIdx.x] : 0;
    s[threadIdx.x] = v;
    __syncthreads();
#pragma unroll
    for (int d = 1; d < 256; d <<= 1) {
        int t = (threadIdx.x >= d) ? s[threadIdx.x - d] : 0;
        __syncthreads();
        s[threadIdx.x] += t;
        __syncthreads();
    }
    if (threadIdx.x < nb) bsum[threadIdx.x] = s[threadIdx.x] - v;
}

__global__ void scan3_kernel(int* off, int* cur, const int* __restrict__ bsum, int N) {
    int i = blockIdx.x * SCAN_T + threadIdx.x;
    if (i < N) {
        int o = off[i] + bsum[blockIdx.x];
        off[i] = o;
        cur[i] = o;
    }
}

__global__ void fill_kernel(int* cur, int* csr, const int* __restrict__ row,
                            const int* __restrict__ col, int E) {
    int i = blockIdx.x * blockDim.x + threadIdx.x;
    if (i < E) {
        int pos = atomicAdd(&cur[col[i]], 1);
        csr[pos] = row[i];
    }
}

// ================= gather aggregation over node range [nBegin,nEnd) =================

__global__ void __launch_bounds__(256) agg_gather_kernel(
    const float* __restrict__ t, float* __restrict__ h,
    const int* __restrict__ csr, const int* __restrict__ off, const int* __restrict__ cnt,
    const float* __restrict__ dinv, const float* __restrict__ b, int nBegin, int nEnd) {
    int n = nBegin + ((blockIdx.x * blockDim.x + threadIdx.x) >> 5);
    if (n >= nEnd) return;
    int lane = threadIdx.x & 31;
    float di = __ldg(&dinv[n]);
    int start = __ldg(&off[n]);
    int m = __ldg(&cnt[n]);
    float4 bb = __ldg(reinterpret_cast<const float4*>(&b[lane * 4]));
    float4 tv = *reinterpret_cast<const float4*>(&t[(size_t)n * CC + lane * 4]);
    float s2 = di * di;
    float4 acc;
    acc.x = bb.x + s2 * tv.x;
    acc.y = bb.y + s2 * tv.y;
    acc.z = bb.z + s2 * tv.z;
    acc.w = bb.w + s2 * tv.w;
    int k = 0;
    for (; k + 4 <= m; k += 4) {
        int r0 = __ldg(&csr[start + k]);
        int r1 = __ldg(&csr[start + k + 1]);
        int r2 = __ldg(&csr[start + k + 2]);
        int r3 = __ldg(&csr[start + k + 3]);
        float w0 = di * __ldg(&dinv[r0]);
        float w1 = di * __ldg(&dinv[r1]);
        float w2 = di * __ldg(&dinv[r2]);
        float w3 = di * __ldg(&dinv[r3]);
        float4 v0 = *reinterpret_cast<const float4*>(&t[(size_t)r0 * CC + lane * 4]);
        float4 v1 = *reinterpret_cast<const float4*>(&t[(size_t)r1 * CC + lane * 4]);
        float4 v2 = *reinterpret_cast<const float4*>(&t[(size_t)r2 * CC + lane * 4]);
        float4 v3 = *reinterpret_cast<const float4*>(&t[(size_t)r3 * CC + lane * 4]);
        acc.x += w0 * v0.x + w1 * v1.x + w2 * v2.x + w3 * v3.x;
        acc.y += w0 * v0.y + w1 * v1.y + w2 * v2.y + w3 * v3.y;
        acc.z += w0 * v0.z + w1 * v1.z + w2 * v2.z + w3 * v3.z;
        acc.w += w0 * v0.w + w1 * v1.w + w2 * v2.w + w3 * v3.w;
    }
    for (; k < m; k++) {
        int r0 = __ldg(&csr[start + k]);
        float w0 = di * __ldg(&dinv[r0]);
        float4 v0 = *reinterpret_cast<const float4*>(&t[(size_t)r0 * CC + lane * 4]);
        acc.x += w0 * v0.x;
        acc.y += w0 * v0.y;
        acc.z += w0 * v0.z;
        acc.w += w0 * v0.w;
    }
    *reinterpret_cast<float4*>(&h[(size_t)n * CC + lane * 4]) = acc;
}

// ================= all weight prep in one launch =================

__global__ void wt_prep_all_kernel(const float* __restrict__ W1,
                                   const float* __restrict__ W2,
                                   const float* __restrict__ Wm1,
                                   __nv_bfloat16* __restrict__ wt) {
    int g = blockIdx.x * blockDim.x + threadIdx.x;
    if (g >= 4 * 128 * 128) return;
    int which = g >> 14;
    int idx = g & 16383;
    int n = idx >> 7;
    int k = idx & 127;
    const float* W = (which == 0) ? W1 : (which == 1) ? W2 : Wm1;
    int koff = (which == 3) ? 128 : 0;
    float v = W[(size_t)(k + koff) * 128 + n];
    __nv_bfloat16 hi = __float2bfloat16_rn(v);
    __nv_bfloat16 lo = __float2bfloat16_rn(v - __bfloat162float(hi));
    wt[(size_t)which * 32768 + idx] = hi;
    wt[(size_t)which * 32768 + 16384 + idx] = lo;
}

// ================= node GEMM on mma.sync (row range [mBegin, mEnd)) =================
#define G_AH 0
#define G_AL 16384
#define G_BH 32768
#define G_BL 49152
#define G_SMEM 65536

__global__ void __launch_bounds__(256, 2) gemm_mma_kernel(
    const float* __restrict__ A,
    const __nv_bfloat16* __restrict__ WTh, const __nv_bfloat16* __restrict__ WTl,
    float* __restrict__ C, int mBegin, int mEnd, int relu_in) {
    extern __shared__ char smem[];
    uint32_t sA = smem_u32(smem);
    int tid = threadIdx.x;
    int lane = tid & 31, wid = tid >> 5;
    int wm = (wid & 3) * 32;
    int wn = (wid >> 2) * 64;
    int m0 = mBegin + blockIdx.x * 128;

    float acc[2][8][4];
#pragma unroll
    for (int mt = 0; mt < 2; mt++)
#pragma unroll
        for (int nt = 0; nt < 8; nt++)
#pragma unroll
            for (int j = 0; j < 4; j++) acc[mt][nt][j] = 0.f;

    const uint4* BHv = (const uint4*)WTh;
    const uint4* BLv = (const uint4*)WTl;

    float4 aR[8];
#pragma unroll
    for (int i = 0; i < 8; i++) {
        int g = tid + i * 256;
        int r = g >> 4, c4 = g & 15;
        int gm = m0 + r;
        aR[i] = make_float4(0.f, 0.f, 0.f, 0.f);
        if (gm < mEnd) aR[i] = *reinterpret_cast<const float4*>(&A[(size_t)gm * CC + c4 * 4]);
    }

    for (int c = 0; c < 2; c++) {
        if (c) __syncthreads();
#pragma unroll
        for (int i = 0; i < 8; i++) {
            int g = tid + i * 256;
            int r = g >> 4, c4 = g & 15;
            float4 v = aR[i];
            if (relu_in) {
                v.x = fmaxf(v.x, 0.f); v.y = fmaxf(v.y, 0.f);
                v.z = fmaxf(v.z, 0.f); v.w = fmaxf(v.w, 0.f);
            }
            uint32_t off = SWZ128((uint32_t)(r * 128 + c4 * 8));
            split_store(smem, G_AH + off, G_AL + off, v);
        }
#pragma unroll
        for (int i = 0; i < 4; i++) {
            int g = tid + i * 256;
            int n = g >> 3;
            int u = g & 7;
            uint32_t off = SWZ128((uint32_t)(n * 128 + u * 16));
            int gi = n * 16 + c * 8 + u;
            *reinterpret_cast<uint4*>(smem + G_BH + off) = BHv[gi];
            *reinterpret_cast<uint4*>(smem + G_BL + off) = BLv[gi];
        }
        __syncthreads();

        if (c == 0) {
#pragma unroll
            for (int i = 0; i < 8; i++) {
                int g = tid + i * 256;
                int r = g >> 4, c4 = g & 15;
                int gm = m0 + r;
                aR[i] = make_float4(0.f, 0.f, 0.f, 0.f);
                if (gm < mEnd) aR[i] = *reinterpret_cast<const float4*>(&A[(size_t)gm * CC + 64 + c4 * 4]);
            }
        }

#pragma unroll
        for (int ks = 0; ks < 4; ks++) {
            int kb = ks * 32;
            uint32_t ah[2][4], al[2][4];
#pragma unroll
            for (int mt = 0; mt < 2; mt++) {
                uint32_t offA = SWZ128((uint32_t)((wm + mt * 16 + (lane & 15)) * 128 +
                                                  kb + (lane & 16)));
                ldsm_x4(sA + G_AH + offA, ah[mt]);
                ldsm_x4(sA + G_AL + offA, al[mt]);
            }
#pragma unroll
            for (int nt2 = 0; nt2 < 4; nt2++) {
                uint32_t offB = SWZ128((uint32_t)((wn + nt2 * 16 + (lane & 7) +
                                                   ((lane & 16) >> 1)) * 128 +
                                                  kb + ((lane & 8) << 1)));
                uint32_t bb[4];
                ldsm_x4(sA + G_BH + offB, bb);
#pragma unroll
                for (int mt = 0; mt < 2; mt++) {
                    mma_bf16(acc[mt][nt2 * 2], ah[mt], bb[0], bb[1]);
                    mma_bf16(acc[mt][nt2 * 2 + 1], ah[mt], bb[2], bb[3]);
                    mma_bf16(acc[mt][nt2 * 2], al[mt], bb[0], bb[1]);
                    mma_bf16(acc[mt][nt2 * 2 + 1], al[mt], bb[2], bb[3]);
                }
                ldsm_x4(sA + G_BL + offB, bb);
#pragma unroll
                for (int mt = 0; mt < 2; mt++) {
                    mma_bf16(acc[mt][nt2 * 2], ah[mt], bb[0], bb[1]);
                    mma_bf16(acc[mt][nt2 * 2 + 1], ah[mt], bb[2], bb[3]);
                }
            }
        }
    }

#pragma unroll
    for (int mt = 0; mt < 2; mt++) {
        int r0 = m0 + wm + mt * 16 + (lane >> 2);
#pragma unroll
        for (int nt = 0; nt < 8; nt++) {
            int col = wn + nt * 8 + (lane & 3) * 2;
            if (r0 < mEnd)
                *reinterpret_cast<float2*>(&C[(size_t)r0 * CC + col]) =
                    make_float2(acc[mt][nt][0], acc[mt][nt][1]);
            if (r0 + 8 < mEnd)
                *reinterpret_cast<float2*>(&C[(size_t)(r0 + 8) * CC + col]) =
                    make_float2(acc[mt][nt][2], acc[mt][nt][3]);
        }
    }
}

// ================= dual-B GEMM (row range) =================
#define D_AH(c) ((uint32_t)(c) * 16384u)
#define D_AL(c) (32768u + (uint32_t)(c) * 16384u)
#define D_BH 65536u
#define D_BL 81920u
#define D_SMEM 98304

__global__ void __launch_bounds__(256, 2) gemm_dual_kernel(
    const float* __restrict__ A,
    const __nv_bfloat16* __restrict__ WTah, const __nv_bfloat16* __restrict__ WTal,
    const __nv_bfloat16* __restrict__ WTbh, const __nv_bfloat16* __restrict__ WTbl,
    float* __restrict__ C1, float* __restrict__ C2, int mBegin, int mEnd) {
    extern __shared__ char smem[];
    uint32_t sA = smem_u32(smem);
    int tid = threadIdx.x;
    int lane = tid & 31, wid = tid >> 5;
    int wm = (wid & 3) * 32;
    int wn = (wid >> 2) * 64;
    int m0 = mBegin + blockIdx.x * 128;

#pragma unroll
    for (int i = 0; i < 16; i++) {
        int g = tid + i * 256;
        int r = g >> 5;
        int c4 = g & 31;
        int chunk = c4 >> 4;
        int gm = m0 + r;
        float4 v = make_float4(0.f, 0.f, 0.f, 0.f);
        if (gm < mEnd) v = *reinterpret_cast<const float4*>(&A[(size_t)gm * CC + c4 * 4]);
        uint32_t off = SWZ128((uint32_t)(r * 128 + (c4 & 15) * 8));
        split_store(smem, D_AH(chunk) + off, D_AL(chunk) + off, v);
    }

    uint4 bhR[4], blR[4];
#pragma unroll
    for (int i = 0; i < 4; i++) {
        int g = tid + i * 256;
        int n = g >> 3, u = g & 7;
        int gi = n * 16 + u;
        bhR[i] = ((const uint4*)WTah)[gi];
        blR[i] = ((const uint4*)WTal)[gi];
    }

    for (int which = 0; which < 2; which++) {
        float* C = (which == 0) ? C1 : C2;

        float acc[2][8][4];
#pragma unroll
        for (int mt = 0; mt < 2; mt++)
#pragma unroll
            for (int nt = 0; nt < 8; nt++)
#pragma unroll
                for (int j = 0; j < 4; j++) acc[mt][nt][j] = 0.f;

        for (int c = 0; c < 2; c++) {
            int p = which * 2 + c;
            if (p) __syncthreads();
#pragma unroll
            for (int i = 0; i < 4; i++) {
                int g = tid + i * 256;
                int n = g >> 3, u = g & 7;
                uint32_t offb = SWZ128((uint32_t)(n * 128 + u * 16));
                *reinterpret_cast<uint4*>(smem + D_BH + offb) = bhR[i];
                *reinterpret_cast<uint4*>(smem + D_BL + offb) = blR[i];
            }
            __syncthreads();
            if (p < 3) {
                int np = p + 1;
                const uint4* H = (np < 2) ? (const uint4*)WTah : (const uint4*)WTbh;
                const uint4* L = (np < 2) ? (const uint4*)WTal : (const uint4*)WTbl;
                int nc = np & 1;
#pragma unroll
                for (int i = 0; i < 4; i++) {
                    int g = tid + i * 256;
                    int n = g >> 3, u = g & 7;
                    int gi = n * 16 + nc * 8 + u;
                    bhR[i] = H[gi];
                    blR[i] = L[gi];
                }
            }

#pragma unroll
            for (int ks = 0; ks < 4; ks++) {
                int kb = ks * 32;
                uint32_t ah[2][4], al[2][4];
#pragma unroll
                for (int mt = 0; mt < 2; mt++) {
                    uint32_t offA = SWZ128((uint32_t)((wm + mt * 16 + (lane & 15)) * 128 +
                                                      kb + (lane & 16)));
                    ldsm_x4(sA + D_AH(c) + offA, ah[mt]);
                    ldsm_x4(sA + D_AL(c) + offA, al[mt]);
                }
#pragma unroll
                for (int nt2 = 0; nt2 < 4; nt2++) {
                    uint32_t offB = SWZ128((uint32_t)((wn + nt2 * 16 + (lane & 7) +
                                                       ((lane & 16) >> 1)) * 128 +
                                                      kb + ((lane & 8) << 1)));
                    uint32_t bb[4];
                    ldsm_x4(sA + D_BH + offB, bb);
#pragma unroll
                    for (int mt = 0; mt < 2; mt++) {
                        mma_bf16(acc[mt][nt2 * 2], ah[mt], bb[0], bb[1]);
                        mma_bf16(acc[mt][nt2 * 2 + 1], ah[mt], bb[2], bb[3]);
                        mma_bf16(acc[mt][nt2 * 2], al[mt], bb[0], bb[1]);
                        mma_bf16(acc[mt][nt2 * 2 + 1], al[mt], bb[2], bb[3]);
                    }
                    ldsm_x4(sA + D_BL + offB, bb);
#pragma unroll
                    for (int mt = 0; mt < 2; mt++) {
                        mma_bf16(acc[mt][nt2 * 2], ah[mt], bb[0], bb[1]);
                        mma_bf16(acc[mt][nt2 * 2 + 1], ah[mt], bb[2], bb[3]);
                    }
                }
            }
        }

#pragma unroll
        for (int mt = 0; mt < 2; mt++) {
            int r0 = m0 + wm + mt * 16 + (lane >> 2);
#pragma unroll
            for (int nt = 0; nt < 8; nt++) {
                int col = wn + nt * 8 + (lane & 3) * 2;
                if (r0 < mEnd)
                    *reinterpret_cast<float2*>(&C[(size_t)r0 * CC + col]) =
                        make_float2(acc[mt][nt][0], acc[mt][nt][1]);
                if (r0 + 8 < mEnd)
                    *reinterpret_cast<float2*>(&C[(size_t)(r0 + 8) * CC + col]) =
                        make_float2(acc[mt][nt][2], acc[mt][nt][3]);
            }
        }
    }
}

// ================= pair stage =================

__global__ void __launch_bounds__(256) pair_kernel(
    const float* __restrict__ Z1, const float* __restrict__ Z2,
    const int* __restrict__ src, const int* __restrict__ dst,
    const float* __restrict__ bm1, const float* __restrict__ Wm2,
    const float* __restrict__ bm2,
    float* __restrict__ out, int P) {
    int gw = (blockIdx.x * blockDim.x + threadIdx.x) >> 5;
    if (gw >= P) return;
    int lane = threadIdx.x & 31;
    int s = __ldg(&src[gw]);
    int d = __ldg(&dst[gw]);
    float4 a = *reinterpret_cast<const float4*>(&Z1[(size_t)s * CC + lane * 4]);
    float4 b = *reinterpret_cast<const float4*>(&Z2[(size_t)d * CC + lane * 4]);
    float4 bb = __ldg(reinterpret_cast<const float4*>(&bm1[lane * 4]));
    float4 w = __ldg(reinterpret_cast<const float4*>(&Wm2[lane * 4]));
    float sum = fmaxf(a.x + b.x + bb.x, 0.f) * w.x
              + fmaxf(a.y + b.y + bb.y, 0.f) * w.y
              + fmaxf(a.z + b.z + bb.z, 0.f) * w.z
              + fmaxf(a.w + b.w + bb.w, 0.f) * w.w;
#pragma unroll
    for (int o = 16; o > 0; o >>= 1) sum += __shfl_xor_sync(0xFFFFFFFFu, sum, o);
    if (lane == 0) out[gw] = sum + __ldg(&bm2[0]);
}

// ================= launch =================

extern "C" void kernel_launch(void* const* d_in, const int* in_sizes, int n_in,
                              void* d_out, int out_size) {
    const float* x = (const float*)d_in[0];
    const int* edge_index = (const int*)d_in[1];
    const int* edge_pairs = (const int*)d_in[2];
    const float* W1 = (const float*)d_in[3];
    const float* b1 = (const float*)d_in[4];
    const float* W2 = (const float*)d_in[5];
    const float* b2 = (const float*)d_in[6];
    const float* Wm1 = (const float*)d_in[7];
    const float* bm1 = (const float*)d_in[8];
    const float* Wm2 = (const float*)d_in[9];
    const float* bm2 = (const float*)d_in[10];
    float* out = (float*)d_out;

    int N = in_sizes[0] / CC;
    int E = in_sizes[1] / 2;
    int P = in_sizes[2] / 2;
    const int* row = edge_index;
    const int* col = edge_index + E;
    const int* src = edge_pairs;
    const int* dst = edge_pairs + P;

    float *d_dinv, *d_t, *d_h, *d_t2, *d_h2, *d_z1, *d_z2;
    int *d_cnt, *d_off, *d_cur, *d_bsum, *d_csr;
    __nv_bfloat16* d_wt;
    cudaGetSymbolAddress((void**)&d_dinv, g_deg);
    cudaGetSymbolAddress((void**)&d_t, g_t);
    cudaGetSymbolAddress((void**)&d_h, g_h);
    cudaGetSymbolAddress((void**)&d_t2, g_t2);
    cudaGetSymbolAddress((void**)&d_h2, g_h2);
    cudaGetSymbolAddress((void**)&d_z1, g_z1);
    cudaGetSymbolAddress((void**)&d_z2, g_z2);
    cudaGetSymbolAddress((void**)&d_cnt, g_cnt);
    cudaGetSymbolAddress((void**)&d_off, g_off);
    cudaGetSymbolAddress((void**)&d_cur, g_cur);
    cudaGetSymbolAddress((void**)&d_bsum, g_bsum);
    cudaGetSymbolAddress((void**)&d_csr, g_csr);
    cudaGetSymbolAddress((void**)&d_wt, g_wt);
    __nv_bfloat16* wt1h = d_wt + 0 * 32768;
    __nv_bfloat16* wt1l = wt1h + 16384;
    __nv_bfloat16* wt2h = d_wt + 1 * 32768;
    __nv_bfloat16* wt2l = wt2h + 16384;
    __nv_bfloat16* wtah = d_wt + 2 * 32768;
    __nv_bfloat16* wtal = wtah + 16384;
    __nv_bfloat16* wtbh = d_wt + 3 * 32768;
    __nv_bfloat16* wtbl = wtbh + 16384;

    cudaFuncSetAttribute(gemm_mma_kernel, cudaFuncAttributeMaxDynamicSharedMemorySize, G_SMEM);
    cudaFuncSetAttribute(gemm_dual_kernel, cudaFuncAttributeMaxDynamicSharedMemorySize, D_SMEM);

    // streams + events created once on the (non-captured) correctness call
    static cudaStream_t s2 = nullptr, sB = nullptr;
    static cudaEvent_t evFork = nullptr, evJoin = nullptr, evT = nullptr;
    static cudaEvent_t evA[NCHUNK], evB, evC[NCHUNK], evD;
    if (s2 == nullptr) {
        cudaStreamCreateWithFlags(&s2, cudaStreamNonBlocking);
        cudaStreamCreateWithFlags(&sB, cudaStreamNonBlocking);
        cudaEventCreateWithFlags(&evFork, cudaEventDisableTiming);
        cudaEventCreateWithFlags(&evJoin, cudaEventDisableTiming);
        cudaEventCreateWithFlags(&evT, cudaEventDisableTiming);
        for (int i = 0; i < NCHUNK; i++) {
            cudaEventCreateWithFlags(&evA[i], cudaEventDisableTiming);
            cudaEventCreateWithFlags(&evC[i], cudaEventDisableTiming);
        }
        cudaEventCreateWithFlags(&evB, cudaEventDisableTiming);
        cudaEventCreateWithFlags(&evD, cudaEventDisableTiming);
    }

    int nScanBlocks = (N + SCAN_T - 1) / SCAN_T;
    int gemmGrid = (N + 127) / 128;

    // chunk boundaries (multiples of 128)
    int chunkSz = (((N + NCHUNK - 1) / NCHUNK + 127) / 128) * 128;
    int cb[NCHUNK + 1];
    for (int i = 0; i <= NCHUNK; i++) {
        int v = i * chunkSz;
        cb[i] = (v > N) ? N : v;
    }

    // main: weight prep
    wt_prep_all_kernel<<<256, 256>>>(W1, W2, Wm1, d_wt);

    // fork: CSR build on s2 (overlaps layer-1 GEMM)
    cudaEventRecord(evFork, 0);
    cudaStreamWaitEvent(s2, evFork, 0);
    zero_cnt_kernel<<<(N + 255) / 256, 256, 0, s2>>>(d_cnt, N);
    hist_kernel<<<(E + 255) / 256, 256, 0, s2>>>(d_cnt, col, E);
    scan1_kernel<<<nScanBlocks, SCAN_T, 0, s2>>>(d_cnt, d_off, d_bsum, d_dinv, N);
    scan2_kernel<<<1, 256, 0, s2>>>(d_bsum, nScanBlocks);
    scan3_kernel<<<nScanBlocks, SCAN_T, 0, s2>>>(d_off, d_cur, d_bsum, N);
    fill_kernel<<<(E + 255) / 256, 256, 0, s2>>>(d_cur, d_csr, row, col, E);
    cudaEventRecord(evJoin, s2);

    // main: layer-1 GEMM  x @ W1 -> t
    gemm_mma_kernel<<<gemmGrid, 256, G_SMEM>>>(x, wt1h, wt1l, d_t, 0, N, 0);
    cudaEventRecord(evT, 0);

    // ---- phase 1: agg1 chunks (main) pipelined with gemm2 chunks (sB) ----
    cudaStreamWaitEvent(0, evJoin, 0);
    for (int c = 0; c < NCHUNK; c++) {
        int len = cb[c + 1] - cb[c];
        if (len <= 0) { cudaEventRecord(evA[c], 0); continue; }
        agg_gather_kernel<<<(len * 32 + 255) / 256, 256>>>(
            d_t, d_h, d_csr, d_off, d_cnt, d_dinv, b1, cb[c], cb[c + 1]);
        cudaEventRecord(evA[c], 0);
    }
    for (int c = 0; c < NCHUNK; c++) {
        int len = cb[c + 1] - cb[c];
        if (len <= 0) continue;
        cudaStreamWaitEvent(sB, evA[c], 0);
        gemm_mma_kernel<<<(len + 127) / 128, 256, G_SMEM, sB>>>(
            d_h, wt2h, wt2l, d_t2, cb[c], cb[c + 1], 1);
    }
    cudaEventRecord(evB, sB);

    // ---- phase 2: agg2 chunks (main) pipelined with dual chunks (sB) ----
    cudaStreamWaitEvent(0, evB, 0);   // agg2 gathers from all of t2
    for (int c = 0; c < NCHUNK; c++) {
        int len = cb[c + 1] - cb[c];
        if (len <= 0) { cudaEventRecord(evC[c], 0); continue; }
        agg_gather_kernel<<<(len * 32 + 255) / 256, 256>>>(
            d_t2, d_h2, d_csr, d_off, d_cnt, d_dinv, b2, cb[c], cb[c + 1]);
        cudaEventRecord(evC[c], 0);
    }
    for (int c = 0; c < NCHUNK; c++) {
        int len = cb[c + 1] - cb[c];
        if (len <= 0) continue;
        cudaStreamWaitEvent(sB, evC[c], 0);
        gemm_dual_kernel<<<(len + 127) / 128, 256, D_SMEM, sB>>>(
            d_h2, wtah, wtal, wtbh, wtbl, d_z1, d_z2, cb[c], cb[c + 1]);
    }
    cudaEventRecord(evD, sB);

    // pair stage needs all z1/z2
    cudaStreamWaitEvent(0, evD, 0);
    pair_kernel<<<(P + 7) / 8, 256>>>(d_z1, d_z2, src, dst, bm1, Wm2, bm2, out, P);
}

// round 12
// speedup vs baseline: 1.1096x; 1.1096x over previous
#include <cuda_runtime.h>
#include <cuda_bf16.h>
#include <cstdint>

#define CC 128
#define MAX_N 100000
#define MAX_E 1600000
#define SCAN_T 512

__device__ float g_deg[MAX_N];           // dinv
__device__ float g_t[(size_t)MAX_N * CC];
__device__ float g_h[(size_t)MAX_N * CC];
__device__ float g_z1[(size_t)MAX_N * CC];
__device__ float g_z2[(size_t)MAX_N * CC];
__device__ int g_cnt[MAX_N];
__device__ int g_off[MAX_N];
__device__ int g_cur[MAX_N];
__device__ int g_bsum[256];
__device__ int g_csr[MAX_E];
// transposed hi/lo weights: [which][hi/lo][n*128+k]
__device__ __nv_bfloat16 g_wt[4][2][128 * 128];

// ================= helpers =================

__device__ __forceinline__ uint32_t smem_u32(const void* p) {
    uint32_t a;
    asm("{ .reg .u64 t; cvta.to.shared.u64 t, %1; cvt.u32.u64 %0, t; }" : "=r"(a) : "l"(p));
    return a;
}

#define SWZ128(o) ((o) ^ (((o) >> 3) & 0x70))

__device__ __forceinline__ void ldsm_x4(uint32_t addr, uint32_t* r) {
    asm volatile("ldmatrix.sync.aligned.m8n8.x4.shared.b16 {%0,%1,%2,%3}, [%4];"
                 : "=r"(r[0]), "=r"(r[1]), "=r"(r[2]), "=r"(r[3]) : "r"(addr));
}

__device__ __forceinline__ void mma_bf16(float* d, const uint32_t* a, uint32_t b0, uint32_t b1) {
    asm volatile("mma.sync.aligned.m16n8k16.row.col.f32.bf16.bf16.f32 "
                 "{%0,%1,%2,%3}, {%4,%5,%6,%7}, {%8,%9}, {%0,%1,%2,%3};"
                 : "+f"(d[0]), "+f"(d[1]), "+f"(d[2]), "+f"(d[3])
                 : "r"(a[0]), "r"(a[1]), "r"(a[2]), "r"(a[3]), "r"(b0), "r"(b1));
}

__device__ __forceinline__ uint32_t pack_bf16(__nv_bfloat16 lo, __nv_bfloat16 hi) {
    return ((uint32_t)__bfloat16_as_ushort(hi) << 16) | (uint32_t)__bfloat16_as_ushort(lo);
}

__device__ __forceinline__ void split_store(char* smem, uint32_t offH, uint32_t offL, float4 v) {
    __nv_bfloat16 hx = __float2bfloat16_rn(v.x);
    __nv_bfloat16 hy = __float2bfloat16_rn(v.y);
    __nv_bfloat16 hz = __float2bfloat16_rn(v.z);
    __nv_bfloat16 hw = __float2bfloat16_rn(v.w);
    __nv_bfloat16 lx = __float2bfloat16_rn(v.x - __bfloat162float(hx));
    __nv_bfloat16 ly = __float2bfloat16_rn(v.y - __bfloat162float(hy));
    __nv_bfloat16 lz = __float2bfloat16_rn(v.z - __bfloat162float(hz));
    __nv_bfloat16 lw = __float2bfloat16_rn(v.w - __bfloat162float(hw));
    *reinterpret_cast<uint2*>(smem + offH) = make_uint2(pack_bf16(hx, hy), pack_bf16(hz, hw));
    *reinterpret_cast<uint2*>(smem + offL) = make_uint2(pack_bf16(lx, ly), pack_bf16(lz, lw));
}

// ================= CSR build =================

__global__ void zero_cnt_kernel(int* cnt, int N) {
    int i = blockIdx.x * blockDim.x + threadIdx.x;
    if (i < N) cnt[i] = 0;
}

__global__ void hist_kernel(int* cnt, const int* __restrict__ col, int E) {
    int i = blockIdx.x * blockDim.x + threadIdx.x;
    if (i < E) atomicAdd(&cnt[col[i]], 1);
}

// scan1 also computes dinv = rsqrt(cnt+1)
__global__ void scan1_kernel(const int* __restrict__ cnt, int* excl, int* bsum,
                             float* dinv, int N) {
    __shared__ int s[SCAN_T];
    int i = blockIdx.x * SCAN_T + threadIdx.x;
    int v = (i < N) ? cnt[i] : 0;
    if (i < N) dinv[i] = rsqrtf((float)v + 1.0f);
    s[threadIdx.x] = v;
    __syncthreads();
#pragma unroll
    for (int d = 1; d < SCAN_T; d <<= 1) {
        int t = (threadIdx.x >= d) ? s[threadIdx.x - d] : 0;
        __syncthreads();
        s[threadIdx.x] += t;
        __syncthreads();
    }
    if (i < N) excl[i] = s[threadIdx.x] - v;
    if (threadIdx.x == SCAN_T - 1) bsum[blockIdx.x] = s[SCAN_T - 1];
}

__global__ void scan2_kernel(int* bsum, int nb) {
    __shared__ int s[256];
    int v = (threadIdx.x < nb) ? bsum[threadIdx.x] : 0;
    s[threadIdx.x] = v;
    __syncthreads();
#pragma unroll
    for (int d = 1; d < 256; d <<= 1) {
        int t = (threadIdx.x >= d) ? s[threadIdx.x - d] : 0;
        __syncthreads();
        s[threadIdx.x] += t;
        __syncthreads();
    }
    if (threadIdx.x < nb) bsum[threadIdx.x] = s[threadIdx.x] - v;  // exclusive
}

__global__ void scan3_kernel(int* off, int* cur, const int* __restrict__ bsum, int N) {
    int i = blockIdx.x * SCAN_T + threadIdx.x;
    if (i < N) {
        int o = off[i] + bsum[blockIdx.x];
        off[i] = o;
        cur[i] = o;
    }
}

__global__ void fill_kernel(int* cur, int* csr, const int* __restrict__ row,
                            const int* __restrict__ col, int E) {
    int i = blockIdx.x * blockDim.x + threadIdx.x;
    if (i < E) {
        int pos = atomicAdd(&cur[col[i]], 1);
        csr[pos] = row[i];
    }
}

// ================= gather aggregation (init + self-loop fused) =================

__global__ void __launch_bounds__(256) agg_gather_kernel(
    const float* __restrict__ t, float* __restrict__ h,
    const int* __restrict__ csr, const int* __restrict__ off, const int* __restrict__ cnt,
    const float* __restrict__ dinv, const float* __restrict__ b, int N) {
    int n = (blockIdx.x * blockDim.x + threadIdx.x) >> 5;
    if (n >= N) return;
    int lane = threadIdx.x & 31;
    float di = __ldg(&dinv[n]);
    int start = __ldg(&off[n]);
    int m = __ldg(&cnt[n]);
    float4 bb = __ldg(reinterpret_cast<const float4*>(&b[lane * 4]));
    float4 tv = *reinterpret_cast<const float4*>(&t[(size_t)n * CC + lane * 4]);
    float s2 = di * di;
    float4 acc;
    acc.x = bb.x + s2 * tv.x;
    acc.y = bb.y + s2 * tv.y;
    acc.z = bb.z + s2 * tv.z;
    acc.w = bb.w + s2 * tv.w;
    int k = 0;
    for (; k + 4 <= m; k += 4) {
        int r0 = __ldg(&csr[start + k]);
        int r1 = __ldg(&csr[start + k + 1]);
        int r2 = __ldg(&csr[start + k + 2]);
        int r3 = __ldg(&csr[start + k + 3]);
        float w0 = di * __ldg(&dinv[r0]);
        float w1 = di * __ldg(&dinv[r1]);
        float w2 = di * __ldg(&dinv[r2]);
        float w3 = di * __ldg(&dinv[r3]);
        float4 v0 = *reinterpret_cast<const float4*>(&t[(size_t)r0 * CC + lane * 4]);
        float4 v1 = *reinterpret_cast<const float4*>(&t[(size_t)r1 * CC + lane * 4]);
        float4 v2 = *reinterpret_cast<const float4*>(&t[(size_t)r2 * CC + lane * 4]);
        float4 v3 = *reinterpret_cast<const float4*>(&t[(size_t)r3 * CC + lane * 4]);
        acc.x += w0 * v0.x + w1 * v1.x + w2 * v2.x + w3 * v3.x;
        acc.y += w0 * v0.y + w1 * v1.y + w2 * v2.y + w3 * v3.y;
        acc.z += w0 * v0.z + w1 * v1.z + w2 * v2.z + w3 * v3.z;
        acc.w += w0 * v0.w + w1 * v1.w + w2 * v2.w + w3 * v3.w;
    }
    for (; k < m; k++) {
        int r0 = __ldg(&csr[start + k]);
        float w0 = di * __ldg(&dinv[r0]);
        float4 v0 = *reinterpret_cast<const float4*>(&t[(size_t)r0 * CC + lane * 4]);
        acc.x += w0 * v0.x;
        acc.y += w0 * v0.y;
        acc.z += w0 * v0.z;
        acc.w += w0 * v0.w;
    }
    *reinterpret_cast<float4*>(&h[(size_t)n * CC + lane * 4]) = acc;
}

// ================= all weight prep in one launch =================

__global__ void wt_prep_all_kernel(const float* __restrict__ W1,
                                   const float* __restrict__ W2,
                                   const float* __restrict__ Wm1,
                                   __nv_bfloat16* __restrict__ wt) {
    int g = blockIdx.x * blockDim.x + threadIdx.x;
    if (g >= 4 * 128 * 128) return;
    int which = g >> 14;
    int idx = g & 16383;
    int n = idx >> 7;
    int k = idx & 127;
    const float* W = (which == 0) ? W1 : (which == 1) ? W2 : Wm1;
    int koff = (which == 3) ? 128 : 0;
    float v = W[(size_t)(k + koff) * 128 + n];
    __nv_bfloat16 hi = __float2bfloat16_rn(v);
    __nv_bfloat16 lo = __float2bfloat16_rn(v - __bfloat162float(hi));
    wt[(size_t)which * 32768 + idx] = hi;
    wt[(size_t)which * 32768 + 16384 + idx] = lo;
}

// ================= node GEMM on mma.sync (single B, A reg-prefetch pipeline) =================
#define G_AH 0
#define G_AL 16384
#define G_BH 32768
#define G_BL 49152
#define G_SMEM 65536

__global__ void __launch_bounds__(256, 2) gemm_mma_kernel(
    const float* __restrict__ A,
    const __nv_bfloat16* __restrict__ WTh, const __nv_bfloat16* __restrict__ WTl,
    float* __restrict__ C, int M, int relu_in) {
    extern __shared__ char smem[];
    uint32_t sA = smem_u32(smem);
    int tid = threadIdx.x;
    int lane = tid & 31, wid = tid >> 5;
    int wm = (wid & 3) * 32;
    int wn = (wid >> 2) * 64;
    int m0 = blockIdx.x * 128;

    float acc[2][8][4];
#pragma unroll
    for (int mt = 0; mt < 2; mt++)
#pragma unroll
        for (int nt = 0; nt < 8; nt++)
#pragma unroll
            for (int j = 0; j < 4; j++) acc[mt][nt][j] = 0.f;

    const uint4* BHv = (const uint4*)WTh;
    const uint4* BLv = (const uint4*)WTl;

    // prefetch chunk-0 A into regs
    float4 aR[8];
#pragma unroll
    for (int i = 0; i < 8; i++) {
        int g = tid + i * 256;
        int r = g >> 4, c4 = g & 15;
        int gm = m0 + r;
        aR[i] = make_float4(0.f, 0.f, 0.f, 0.f);
        if (gm < M) aR[i] = *reinterpret_cast<const float4*>(&A[(size_t)gm * CC + c4 * 4]);
    }

    for (int c = 0; c < 2; c++) {
        if (c) __syncthreads();
        // convert prefetched A chunk -> bf16 hi/lo smem
#pragma unroll
        for (int i = 0; i < 8; i++) {
            int g = tid + i * 256;
            int r = g >> 4, c4 = g & 15;
            float4 v = aR[i];
            if (relu_in) {
                v.x = fmaxf(v.x, 0.f); v.y = fmaxf(v.y, 0.f);
                v.z = fmaxf(v.z, 0.f); v.w = fmaxf(v.w, 0.f);
            }
            uint32_t off = SWZ128((uint32_t)(r * 128 + c4 * 8));
            split_store(smem, G_AH + off, G_AL + off, v);
        }
        // B chunk
#pragma unroll
        for (int i = 0; i < 4; i++) {
            int g = tid + i * 256;
            int n = g >> 3;
            int u = g & 7;
            uint32_t off = SWZ128((uint32_t)(n * 128 + u * 16));
            int gi = n * 16 + c * 8 + u;
            *reinterpret_cast<uint4*>(smem + G_BH + off) = BHv[gi];
            *reinterpret_cast<uint4*>(smem + G_BL + off) = BLv[gi];
        }
        __syncthreads();

        // issue chunk-1 A loads; latency hidden under chunk-0 MMA
        if (c == 0) {
#pragma unroll
            for (int i = 0; i < 8; i++) {
                int g = tid + i * 256;
                int r = g >> 4, c4 = g & 15;
                int gm = m0 + r;
                aR[i] = make_float4(0.f, 0.f, 0.f, 0.f);
                if (gm < M) aR[i] = *reinterpret_cast<const float4*>(&A[(size_t)gm * CC + 64 + c4 * 4]);
            }
        }

#pragma unroll
        for (int ks = 0; ks < 4; ks++) {
            int kb = ks * 32;
            uint32_t ah[2][4], al[2][4];
#pragma unroll
            for (int mt = 0; mt < 2; mt++) {
                uint32_t offA = SWZ128((uint32_t)((wm + mt * 16 + (lane & 15)) * 128 +
                                                  kb + (lane & 16)));
                ldsm_x4(sA + G_AH + offA, ah[mt]);
                ldsm_x4(sA + G_AL + offA, al[mt]);
            }
#pragma unroll
            for (int nt2 = 0; nt2 < 4; nt2++) {
                uint32_t offB = SWZ128((uint32_t)((wn + nt2 * 16 + (lane & 7) +
                                                   ((lane & 16) >> 1)) * 128 +
                                                  kb + ((lane & 8) << 1)));
                uint32_t bb[4];
                ldsm_x4(sA + G_BH + offB, bb);
#pragma unroll
                for (int mt = 0; mt < 2; mt++) {
                    mma_bf16(acc[mt][nt2 * 2], ah[mt], bb[0], bb[1]);
                    mma_bf16(acc[mt][nt2 * 2 + 1], ah[mt], bb[2], bb[3]);
                    mma_bf16(acc[mt][nt2 * 2], al[mt], bb[0], bb[1]);
                    mma_bf16(acc[mt][nt2 * 2 + 1], al[mt], bb[2], bb[3]);
                }
                ldsm_x4(sA + G_BL + offB, bb);
#pragma unroll
                for (int mt = 0; mt < 2; mt++) {
                    mma_bf16(acc[mt][nt2 * 2], ah[mt], bb[0], bb[1]);
                    mma_bf16(acc[mt][nt2 * 2 + 1], ah[mt], bb[2], bb[3]);
                }
            }
        }
    }

#pragma unroll
    for (int mt = 0; mt < 2; mt++) {
        int r0 = m0 + wm + mt * 16 + (lane >> 2);
#pragma unroll
        for (int nt = 0; nt < 8; nt++) {
            int col = wn + nt * 8 + (lane & 3) * 2;
            if (r0 < M)
                *reinterpret_cast<float2*>(&C[(size_t)r0 * CC + col]) =
                    make_float2(acc[mt][nt][0], acc[mt][nt][1]);
            if (r0 + 8 < M)
                *reinterpret_cast<float2*>(&C[(size_t)(r0 + 8) * CC + col]) =
                    make_float2(acc[mt][nt][2], acc[mt][nt][3]);
        }
    }
}

// ================= dual-B GEMM: Z1 = A@W_a, Z2 = A@W_b (B reg-prefetch pipeline) =================
#define D_AH(c) ((uint32_t)(c) * 16384u)
#define D_AL(c) (32768u + (uint32_t)(c) * 16384u)
#define D_BH 65536u
#define D_BL 81920u
#define D_SMEM 98304

__global__ void __launch_bounds__(256, 2) gemm_dual_kernel(
    const float* __restrict__ A,
    const __nv_bfloat16* __restrict__ WTah, const __nv_bfloat16* __restrict__ WTal,
    const __nv_bfloat16* __restrict__ WTbh, const __nv_bfloat16* __restrict__ WTbl,
    float* __restrict__ C1, float* __restrict__ C2, int M) {
    extern __shared__ char smem[];
    uint32_t sA = smem_u32(smem);
    int tid = threadIdx.x;
    int lane = tid & 31, wid = tid >> 5;
    int wm = (wid & 3) * 32;
    int wn = (wid >> 2) * 64;
    int m0 = blockIdx.x * 128;

    // ---- convert full A (both chunks) once ----
#pragma unroll
    for (int i = 0; i < 16; i++) {
        int g = tid + i * 256;
        int r = g >> 5;
        int c4 = g & 31;
        int chunk = c4 >> 4;
        int gm = m0 + r;
        float4 v = make_float4(0.f, 0.f, 0.f, 0.f);
        if (gm < M) v = *reinterpret_cast<const float4*>(&A[(size_t)gm * CC + c4 * 4]);
        uint32_t off = SWZ128((uint32_t)(r * 128 + (c4 & 15) * 8));
        split_store(smem, D_AH(chunk) + off, D_AL(chunk) + off, v);
    }

    // B tile prefetch registers
    uint4 bhR[4], blR[4];
#pragma unroll
    for (int i = 0; i < 4; i++) {
        int g = tid + i * 256;
        int n = g >> 3, u = g & 7;
        int gi = n * 16 + u;
        bhR[i] = ((const uint4*)WTah)[gi];
        blR[i] = ((const uint4*)WTal)[gi];
    }

    for (int which = 0; which < 2; which++) {
        float* C = (which == 0) ? C1 : C2;

        float acc[2][8][4];
#pragma unroll
        for (int mt = 0; mt < 2; mt++)
#pragma unroll
            for (int nt = 0; nt < 8; nt++)
#pragma unroll
                for (int j = 0; j < 4; j++) acc[mt][nt][j] = 0.f;

        for (int c = 0; c < 2; c++) {
            int p = which * 2 + c;
            if (p) __syncthreads();
#pragma unroll
            for (int i = 0; i < 4; i++) {
                int g = tid + i * 256;
                int n = g >> 3, u = g & 7;
                uint32_t offb = SWZ128((uint32_t)(n * 128 + u * 16));
                *reinterpret_cast<uint4*>(smem + D_BH + offb) = bhR[i];
                *reinterpret_cast<uint4*>(smem + D_BL + offb) = blR[i];
            }
            __syncthreads();
            if (p < 3) {
                int np = p + 1;
                const uint4* H = (np < 2) ? (const uint4*)WTah : (const uint4*)WTbh;
                const uint4* L = (np < 2) ? (const uint4*)WTal : (const uint4*)WTbl;
                int nc = np & 1;
#pragma unroll
                for (int i = 0; i < 4; i++) {
                    int g = tid + i * 256;
                    int n = g >> 3, u = g & 7;
                    int gi = n * 16 + nc * 8 + u;
                    bhR[i] = H[gi];
                    blR[i] = L[gi];
                }
            }

#pragma unroll
            for (int ks = 0; ks < 4; ks++) {
                int kb = ks * 32;
                uint32_t ah[2][4], al[2][4];
#pragma unroll
                for (int mt = 0; mt < 2; mt++) {
                    uint32_t offA = SWZ128((uint32_t)((wm + mt * 16 + (lane & 15)) * 128 +
                                                      kb + (lane & 16)));
                    ldsm_x4(sA + D_AH(c) + offA, ah[mt]);
                    ldsm_x4(sA + D_AL(c) + offA, al[mt]);
                }
#pragma unroll
                for (int nt2 = 0; nt2 < 4; nt2++) {
                    uint32_t offB = SWZ128((uint32_t)((wn + nt2 * 16 + (lane & 7) +
                                                       ((lane & 16) >> 1)) * 128 +
                                                      kb + ((lane & 8) << 1)));
                    uint32_t bb[4];
                    ldsm_x4(sA + D_BH + offB, bb);
#pragma unroll
                    for (int mt = 0; mt < 2; mt++) {
                        mma_bf16(acc[mt][nt2 * 2], ah[mt], bb[0], bb[1]);
                        mma_bf16(acc[mt][nt2 * 2 + 1], ah[mt], bb[2], bb[3]);
                        mma_bf16(acc[mt][nt2 * 2], al[mt], bb[0], bb[1]);
                        mma_bf16(acc[mt][nt2 * 2 + 1], al[mt], bb[2], bb[3]);
                    }
                    ldsm_x4(sA + D_BL + offB, bb);
#pragma unroll
                    for (int mt = 0; mt < 2; mt++) {
                        mma_bf16(acc[mt][nt2 * 2], ah[mt], bb[0], bb[1]);
                        mma_bf16(acc[mt][nt2 * 2 + 1], ah[mt], bb[2], bb[3]);
                    }
                }
            }
        }

#pragma unroll
        for (int mt = 0; mt < 2; mt++) {
            int r0 = m0 + wm + mt * 16 + (lane >> 2);
#pragma unroll
            for (int nt = 0; nt < 8; nt++) {
                int col = wn + nt * 8 + (lane & 3) * 2;
                if (r0 < M)
                    *reinterpret_cast<float2*>(&C[(size_t)r0 * CC + col]) =
                        make_float2(acc[mt][nt][0], acc[mt][nt][1]);
                if (r0 + 8 < M)
                    *reinterpret_cast<float2*>(&C[(size_t)(r0 + 8) * CC + col]) =
                        make_float2(acc[mt][nt][2], acc[mt][nt][3]);
            }
        }
    }
}

// ================= pair stage =================

__global__ void __launch_bounds__(256) pair_kernel(
    const float* __restrict__ Z1, const float* __restrict__ Z2,
    const int* __restrict__ src, const int* __restrict__ dst,
    const float* __restrict__ bm1, const float* __restrict__ Wm2,
    const float* __restrict__ bm2,
    float* __restrict__ out, int P) {
    int gw = (blockIdx.x * blockDim.x + threadIdx.x) >> 5;
    if (gw >= P) return;
    int lane = threadIdx.x & 31;
    int s = __ldg(&src[gw]);
    int d = __ldg(&dst[gw]);
    float4 a = *reinterpret_cast<const float4*>(&Z1[(size_t)s * CC + lane * 4]);
    float4 b = *reinterpret_cast<const float4*>(&Z2[(size_t)d * CC + lane * 4]);
    float4 bb = __ldg(reinterpret_cast<const float4*>(&bm1[lane * 4]));
    float4 w = __ldg(reinterpret_cast<const float4*>(&Wm2[lane * 4]));
    float sum = fmaxf(a.x + b.x + bb.x, 0.f) * w.x
              + fmaxf(a.y + b.y + bb.y, 0.f) * w.y
              + fmaxf(a.z + b.z + bb.z, 0.f) * w.z
              + fmaxf(a.w + b.w + bb.w, 0.f) * w.w;
#pragma unroll
    for (int o = 16; o > 0; o >>= 1) sum += __shfl_xor_sync(0xFFFFFFFFu, sum, o);
    if (lane == 0) out[gw] = sum + __ldg(&bm2[0]);
}

// ================= launch =================

extern "C" void kernel_launch(void* const* d_in, const int* in_sizes, int n_in,
                              void* d_out, int out_size) {
    const float* x = (const float*)d_in[0];
    const int* edge_index = (const int*)d_in[1];
    const int* edge_pairs = (const int*)d_in[2];
    const float* W1 = (const float*)d_in[3];
    const float* b1 = (const float*)d_in[4];
    const float* W2 = (const float*)d_in[5];
    const float* b2 = (const float*)d_in[6];
    const float* Wm1 = (const float*)d_in[7];
    const float* bm1 = (const float*)d_in[8];
    const float* Wm2 = (const float*)d_in[9];
    const float* bm2 = (const float*)d_in[10];
    float* out = (float*)d_out;

    int N = in_sizes[0] / CC;
    int E = in_sizes[1] / 2;
    int P = in_sizes[2] / 2;
    const int* row = edge_index;
    const int* col = edge_index + E;
    const int* src = edge_pairs;
    const int* dst = edge_pairs + P;

    float *d_dinv, *d_t, *d_h, *d_z1, *d_z2;
    int *d_cnt, *d_off, *d_cur, *d_bsum, *d_csr;
    __nv_bfloat16* d_wt;
    cudaGetSymbolAddress((void**)&d_dinv, g_deg);
    cudaGetSymbolAddress((void**)&d_t, g_t);
    cudaGetSymbolAddress((void**)&d_h, g_h);
    cudaGetSymbolAddress((void**)&d_z1, g_z1);
    cudaGetSymbolAddress((void**)&d_z2, g_z2);
    cudaGetSymbolAddress((void**)&d_cnt, g_cnt);
    cudaGetSymbolAddress((void**)&d_off, g_off);
    cudaGetSymbolAddress((void**)&d_cur, g_cur);
    cudaGetSymbolAddress((void**)&d_bsum, g_bsum);
    cudaGetSymbolAddress((void**)&d_csr, g_csr);
    cudaGetSymbolAddress((void**)&d_wt, g_wt);
    __nv_bfloat16* wt1h = d_wt + 0 * 32768;
    __nv_bfloat16* wt1l = wt1h + 16384;
    __nv_bfloat16* wt2h = d_wt + 1 * 32768;
    __nv_bfloat16* wt2l = wt2h + 16384;
    __nv_bfloat16* wtah = d_wt + 2 * 32768;
    __nv_bfloat16* wtal = wtah + 16384;
    __nv_bfloat16* wtbh = d_wt + 3 * 32768;
    __nv_bfloat16* wtbl = wtbh + 16384;

    cudaFuncSetAttribute(gemm_mma_kernel, cudaFuncAttributeMaxDynamicSharedMemorySize, G_SMEM);
    cudaFuncSetAttribute(gemm_dual_kernel, cudaFuncAttributeMaxDynamicSharedMemorySize, D_SMEM);

    // side stream + fork/join events, created once on the (non-captured)
    // correctness call; only event record/wait happens during capture.
    static cudaStream_t s2 = nullptr;
    static cudaEvent_t evFork = nullptr, evJoin = nullptr;
    if (s2 == nullptr) {
        cudaStreamCreateWithFlags(&s2, cudaStreamNonBlocking);
        cudaEventCreateWithFlags(&evFork, cudaEventDisableTiming);
        cudaEventCreateWithFlags(&evJoin, cudaEventDisableTiming);
    }

    int nScanBlocks = (N + SCAN_T - 1) / SCAN_T;
    int gemmGrid = (N + 127) / 128;
    int aggGrid = (N + 7) / 8;

    // main: weight prep (layer-1 GEMM depends on it)
    wt_prep_all_kernel<<<256, 256>>>(W1, W2, Wm1, d_wt);

    // fork: CSR build chain on s2, concurrent with layer-1 GEMM on main
    cudaEventRecord(evFork, 0);
    cudaStreamWaitEvent(s2, evFork, 0);
    zero_cnt_kernel<<<(N + 255) / 256, 256, 0, s2>>>(d_cnt, N);
    hist_kernel<<<(E + 255) / 256, 256, 0, s2>>>(d_cnt, col, E);
    scan1_kernel<<<nScanBlocks, SCAN_T, 0, s2>>>(d_cnt, d_off, d_bsum, d_dinv, N);
    scan2_kernel<<<1, 256, 0, s2>>>(d_bsum, nScanBlocks);
    scan3_kernel<<<nScanBlocks, SCAN_T, 0, s2>>>(d_off, d_cur, d_bsum, N);
    fill_kernel<<<(E + 255) / 256, 256, 0, s2>>>(d_cur, d_csr, row, col, E);
    cudaEventRecord(evJoin, s2);

    // main: layer-1 GEMM (overlaps CSR build)
    gemm_mma_kernel<<<gemmGrid, 256, G_SMEM>>>(x, wt1h, wt1l, d_t, N, 0);

    // join: aggregation needs both CSR and t
    cudaStreamWaitEvent(0, evJoin, 0);
    agg_gather_kernel<<<aggGrid, 256>>>(d_t, d_h, d_csr, d_off, d_cnt, d_dinv, b1, N);

    // layer 2 (relu fused into A-load)
    gemm_mma_kernel<<<gemmGrid, 256, G_SMEM>>>(d_h, wt2h, wt2l, d_t, N, 1);
    agg_gather_kernel<<<aggGrid, 256>>>(d_t, d_h, d_csr, d_off, d_cnt, d_dinv, b2, N);

    // node-level MLP projections (dual B, A converted once)
    gemm_dual_kernel<<<gemmGrid, 256, D_SMEM>>>(d_h, wtah, wtal, wtbh, wtbl, d_z1, d_z2, N);

    // pair stage
    pair_kernel<<<(P + 7) / 8, 256>>>(d_z1, d_z2, src, dst, bm1, Wm2, bm2, out, P);
}

// round 13
// speedup vs baseline: 1.1139x; 1.0039x over previous
#include <cuda_runtime.h>
#include <cuda_bf16.h>
#include <cstdint>

#define CC 128
#define MAX_N 100000
#define MAX_E 1600000
#define SCAN_T 512

__device__ float g_deg[MAX_N];           // dinv
__device__ float g_t[(size_t)MAX_N * CC];
__device__ __nv_bfloat16 g_thi[(size_t)MAX_N * CC];
__device__ __nv_bfloat16 g_tlo[(size_t)MAX_N * CC];
__device__ float g_z1[(size_t)MAX_N * CC];
__device__ float g_z2[(size_t)MAX_N * CC];
__device__ int g_cnt[MAX_N];
__device__ int g_off[MAX_N];
__device__ int g_cur[MAX_N];
__device__ int g_bsum[256];
__device__ int g_csr[MAX_E];
// transposed hi/lo weights: [which][hi/lo][n*128+k]
__device__ __nv_bfloat16 g_wt[4][2][128 * 128];

// ================= helpers =================

__device__ __forceinline__ uint32_t smem_u32(const void* p) {
    uint32_t a;
    asm("{ .reg .u64 t; cvta.to.shared.u64 t, %1; cvt.u32.u64 %0, t; }" : "=r"(a) : "l"(p));
    return a;
}

#define SWZ128(o) ((o) ^ (((o) >> 3) & 0x70))

__device__ __forceinline__ void ldsm_x4(uint32_t addr, uint32_t* r) {
    asm volatile("ldmatrix.sync.aligned.m8n8.x4.shared.b16 {%0,%1,%2,%3}, [%4];"
                 : "=r"(r[0]), "=r"(r[1]), "=r"(r[2]), "=r"(r[3]) : "r"(addr));
}

__device__ __forceinline__ void mma_bf16(float* d, const uint32_t* a, uint32_t b0, uint32_t b1) {
    asm volatile("mma.sync.aligned.m16n8k16.row.col.f32.bf16.bf16.f32 "
                 "{%0,%1,%2,%3}, {%4,%5,%6,%7}, {%8,%9}, {%0,%1,%2,%3};"
                 : "+f"(d[0]), "+f"(d[1]), "+f"(d[2]), "+f"(d[3])
                 : "r"(a[0]), "r"(a[1]), "r"(a[2]), "r"(a[3]), "r"(b0), "r"(b1));
}

__device__ __forceinline__ uint32_t pack_bf16(__nv_bfloat16 lo, __nv_bfloat16 hi) {
    return ((uint32_t)__bfloat16_as_ushort(hi) << 16) | (uint32_t)__bfloat16_as_ushort(lo);
}

__device__ __forceinline__ void split_store(char* smem, uint32_t offH, uint32_t offL, float4 v) {
    __nv_bfloat16 hx = __float2bfloat16_rn(v.x);
    __nv_bfloat16 hy = __float2bfloat16_rn(v.y);
    __nv_bfloat16 hz = __float2bfloat16_rn(v.z);
    __nv_bfloat16 hw = __float2bfloat16_rn(v.w);
    __nv_bfloat16 lx = __float2bfloat16_rn(v.x - __bfloat162float(hx));
    __nv_bfloat16 ly = __float2bfloat16_rn(v.y - __bfloat162float(hy));
    __nv_bfloat16 lz = __float2bfloat16_rn(v.z - __bfloat162float(hz));
    __nv_bfloat16 lw = __float2bfloat16_rn(v.w - __bfloat162float(hw));
    *reinterpret_cast<uint2*>(smem + offH) = make_uint2(pack_bf16(hx, hy), pack_bf16(hz, hw));
    *reinterpret_cast<uint2*>(smem + offL) = make_uint2(pack_bf16(lx, ly), pack_bf16(lz, lw));
}

// ================= CSR build =================

__global__ void zero_cnt_kernel(int* cnt, int N) {
    int i = blockIdx.x * blockDim.x + threadIdx.x;
    if (i < N) cnt[i] = 0;
}

__global__ void hist_kernel(int* cnt, const int* __restrict__ col, int E) {
    int i = blockIdx.x * blockDim.x + threadIdx.x;
    if (i < E) atomicAdd(&cnt[col[i]], 1);
}

// scan1 also computes dinv = rsqrt(cnt+1)
__global__ void scan1_kernel(const int* __restrict__ cnt, int* excl, int* bsum,
                             float* dinv, int N) {
    __shared__ int s[SCAN_T];
    int i = blockIdx.x * SCAN_T + threadIdx.x;
    int v = (i < N) ? cnt[i] : 0;
    if (i < N) dinv[i] = rsqrtf((float)v + 1.0f);
    s[threadIdx.x] = v;
    __syncthreads();
#pragma unroll
    for (int d = 1; d < SCAN_T; d <<= 1) {
        int t = (threadIdx.x >= d) ? s[threadIdx.x - d] : 0;
        __syncthreads();
        s[threadIdx.x] += t;
        __syncthreads();
    }
    if (i < N) excl[i] = s[threadIdx.x] - v;
    if (threadIdx.x == SCAN_T - 1) bsum[blockIdx.x] = s[SCAN_T - 1];
}

__global__ void scan2_kernel(int* bsum, int nb) {
    __shared__ int s[256];
    int v = (threadIdx.x < nb) ? bsum[threadIdx.x] : 0;
    s[threadIdx.x] = v;
    __syncthreads();
#pragma unroll
    for (int d = 1; d < 256; d <<= 1) {
        int t = (threadIdx.x >= d) ? s[threadIdx.x - d] : 0;
        __syncthreads();
        s[threadIdx.x] += t;
        __syncthreads();
    }
    if (threadIdx.x < nb) bsum[threadIdx.x] = s[threadIdx.x] - v;  // exclusive
}

__global__ void scan3_kernel(int* off, int* cur, const int* __restrict__ bsum, int N) {
    int i = blockIdx.x * SCAN_T + threadIdx.x;
    if (i < N) {
        int o = off[i] + bsum[blockIdx.x];
        off[i] = o;
        cur[i] = o;
    }
}

__global__ void fill_kernel(int* cur, int* csr, const int* __restrict__ row,
                            const int* __restrict__ col, int E) {
    int i = blockIdx.x * blockDim.x + threadIdx.x;
    if (i < E) {
        int pos = atomicAdd(&cur[col[i]], 1);
        csr[pos] = row[i];
    }
}

// ================= gather aggregation -> bf16 hi/lo split output =================
// out = (relu?) (bias + dinv^2*t[n] + sum norm*t[csr]) split into bf16 hi/lo.

__global__ void __launch_bounds__(256) agg_gather_split_kernel(
    const float* __restrict__ t,
    __nv_bfloat16* __restrict__ hHi, __nv_bfloat16* __restrict__ hLo,
    const int* __restrict__ csr, const int* __restrict__ off, const int* __restrict__ cnt,
    const float* __restrict__ dinv, const float* __restrict__ b, int relu, int N) {
    int n = (blockIdx.x * blockDim.x + threadIdx.x) >> 5;
    if (n >= N) return;
    int lane = threadIdx.x & 31;
    float di = __ldg(&dinv[n]);
    int start = __ldg(&off[n]);
    int m = __ldg(&cnt[n]);
    float4 bb = __ldg(reinterpret_cast<const float4*>(&b[lane * 4]));
    float4 tv = *reinterpret_cast<const float4*>(&t[(size_t)n * CC + lane * 4]);
    float s2 = di * di;
    float4 acc;
    acc.x = bb.x + s2 * tv.x;
    acc.y = bb.y + s2 * tv.y;
    acc.z = bb.z + s2 * tv.z;
    acc.w = bb.w + s2 * tv.w;
    int k = 0;
    for (; k + 4 <= m; k += 4) {
        int r0 = __ldg(&csr[start + k]);
        int r1 = __ldg(&csr[start + k + 1]);
        int r2 = __ldg(&csr[start + k + 2]);
        int r3 = __ldg(&csr[start + k + 3]);
        float w0 = di * __ldg(&dinv[r0]);
        float w1 = di * __ldg(&dinv[r1]);
        float w2 = di * __ldg(&dinv[r2]);
        float w3 = di * __ldg(&dinv[r3]);
        float4 v0 = *reinterpret_cast<const float4*>(&t[(size_t)r0 * CC + lane * 4]);
        float4 v1 = *reinterpret_cast<const float4*>(&t[(size_t)r1 * CC + lane * 4]);
        float4 v2 = *reinterpret_cast<const float4*>(&t[(size_t)r2 * CC + lane * 4]);
        float4 v3 = *reinterpret_cast<const float4*>(&t[(size_t)r3 * CC + lane * 4]);
        acc.x += w0 * v0.x + w1 * v1.x + w2 * v2.x + w3 * v3.x;
        acc.y += w0 * v0.y + w1 * v1.y + w2 * v2.y + w3 * v3.y;
        acc.z += w0 * v0.z + w1 * v1.z + w2 * v2.z + w3 * v3.z;
        acc.w += w0 * v0.w + w1 * v1.w + w2 * v2.w + w3 * v3.w;
    }
    for (; k < m; k++) {
        int r0 = __ldg(&csr[start + k]);
        float w0 = di * __ldg(&dinv[r0]);
        float4 v0 = *reinterpret_cast<const float4*>(&t[(size_t)r0 * CC + lane * 4]);
        acc.x += w0 * v0.x;
        acc.y += w0 * v0.y;
        acc.z += w0 * v0.z;
        acc.w += w0 * v0.w;
    }
    if (relu) {
        acc.x = fmaxf(acc.x, 0.f); acc.y = fmaxf(acc.y, 0.f);
        acc.z = fmaxf(acc.z, 0.f); acc.w = fmaxf(acc.w, 0.f);
    }
    __nv_bfloat16 hx = __float2bfloat16_rn(acc.x);
    __nv_bfloat16 hy = __float2bfloat16_rn(acc.y);
    __nv_bfloat16 hz = __float2bfloat16_rn(acc.z);
    __nv_bfloat16 hw = __float2bfloat16_rn(acc.w);
    __nv_bfloat16 lx = __float2bfloat16_rn(acc.x - __bfloat162float(hx));
    __nv_bfloat16 ly = __float2bfloat16_rn(acc.y - __bfloat162float(hy));
    __nv_bfloat16 lz = __float2bfloat16_rn(acc.z - __bfloat162float(hz));
    __nv_bfloat16 lw = __float2bfloat16_rn(acc.w - __bfloat162float(hw));
    *reinterpret_cast<uint2*>(&hHi[(size_t)n * CC + lane * 4]) =
        make_uint2(pack_bf16(hx, hy), pack_bf16(hz, hw));
    *reinterpret_cast<uint2*>(&hLo[(size_t)n * CC + lane * 4]) =
        make_uint2(pack_bf16(lx, ly), pack_bf16(lz, lw));
}

// ================= all weight prep in one launch =================

__global__ void wt_prep_all_kernel(const float* __restrict__ W1,
                                   const float* __restrict__ W2,
                                   const float* __restrict__ Wm1,
                                   __nv_bfloat16* __restrict__ wt) {
    int g = blockIdx.x * blockDim.x + threadIdx.x;
    if (g >= 4 * 128 * 128) return;
    int which = g >> 14;
    int idx = g & 16383;
    int n = idx >> 7;
    int k = idx & 127;
    const float* W = (which == 0) ? W1 : (which == 1) ? W2 : Wm1;
    int koff = (which == 3) ? 128 : 0;
    float v = W[(size_t)(k + koff) * 128 + n];
    __nv_bfloat16 hi = __float2bfloat16_rn(v);
    __nv_bfloat16 lo = __float2bfloat16_rn(v - __bfloat162float(hi));
    wt[(size_t)which * 32768 + idx] = hi;
    wt[(size_t)which * 32768 + 16384 + idx] = lo;
}

// ================= node GEMM (fp32 A with convert; used for layer 1 only) =================
#define G_AH 0
#define G_AL 16384
#define G_BH 32768
#define G_BL 49152
#define G_SMEM 65536

__global__ void __launch_bounds__(256, 2) gemm_mma_kernel(
    const float* __restrict__ A,
    const __nv_bfloat16* __restrict__ WTh, const __nv_bfloat16* __restrict__ WTl,
    float* __restrict__ C, int M) {
    extern __shared__ char smem[];
    uint32_t sA = smem_u32(smem);
    int tid = threadIdx.x;
    int lane = tid & 31, wid = tid >> 5;
    int wm = (wid & 3) * 32;
    int wn = (wid >> 2) * 64;
    int m0 = blockIdx.x * 128;

    float acc[2][8][4];
#pragma unroll
    for (int mt = 0; mt < 2; mt++)
#pragma unroll
        for (int nt = 0; nt < 8; nt++)
#pragma unroll
            for (int j = 0; j < 4; j++) acc[mt][nt][j] = 0.f;

    const uint4* BHv = (const uint4*)WTh;
    const uint4* BLv = (const uint4*)WTl;

    float4 aR[8];
#pragma unroll
    for (int i = 0; i < 8; i++) {
        int g = tid + i * 256;
        int r = g >> 4, c4 = g & 15;
        int gm = m0 + r;
        aR[i] = make_float4(0.f, 0.f, 0.f, 0.f);
        if (gm < M) aR[i] = *reinterpret_cast<const float4*>(&A[(size_t)gm * CC + c4 * 4]);
    }

    for (int c = 0; c < 2; c++) {
        if (c) __syncthreads();
#pragma unroll
        for (int i = 0; i < 8; i++) {
            int g = tid + i * 256;
            int r = g >> 4, c4 = g & 15;
            uint32_t off = SWZ128((uint32_t)(r * 128 + c4 * 8));
            split_store(smem, G_AH + off, G_AL + off, aR[i]);
        }
#pragma unroll
        for (int i = 0; i < 4; i++) {
            int g = tid + i * 256;
            int n = g >> 3;
            int u = g & 7;
            uint32_t off = SWZ128((uint32_t)(n * 128 + u * 16));
            int gi = n * 16 + c * 8 + u;
            *reinterpret_cast<uint4*>(smem + G_BH + off) = BHv[gi];
            *reinterpret_cast<uint4*>(smem + G_BL + off) = BLv[gi];
        }
        __syncthreads();

        if (c == 0) {
#pragma unroll
            for (int i = 0; i < 8; i++) {
                int g = tid + i * 256;
                int r = g >> 4, c4 = g & 15;
                int gm = m0 + r;
                aR[i] = make_float4(0.f, 0.f, 0.f, 0.f);
                if (gm < M) aR[i] = *reinterpret_cast<const float4*>(&A[(size_t)gm * CC + 64 + c4 * 4]);
            }
        }

#pragma unroll
        for (int ks = 0; ks < 4; ks++) {
            int kb = ks * 32;
            uint32_t ah[2][4], al[2][4];
#pragma unroll
            for (int mt = 0; mt < 2; mt++) {
                uint32_t offA = SWZ128((uint32_t)((wm + mt * 16 + (lane & 15)) * 128 +
                                                  kb + (lane & 16)));
                ldsm_x4(sA + G_AH + offA, ah[mt]);
                ldsm_x4(sA + G_AL + offA, al[mt]);
            }
#pragma unroll
            for (int nt2 = 0; nt2 < 4; nt2++) {
                uint32_t offB = SWZ128((uint32_t)((wn + nt2 * 16 + (lane & 7) +
                                                   ((lane & 16) >> 1)) * 128 +
                                                  kb + ((lane & 8) << 1)));
                uint32_t bb[4];
                ldsm_x4(sA + G_BH + offB, bb);
#pragma unroll
                for (int mt = 0; mt < 2; mt++) {
                    mma_bf16(acc[mt][nt2 * 2], ah[mt], bb[0], bb[1]);
                    mma_bf16(acc[mt][nt2 * 2 + 1], ah[mt], bb[2], bb[3]);
                    mma_bf16(acc[mt][nt2 * 2], al[mt], bb[0], bb[1]);
                    mma_bf16(acc[mt][nt2 * 2 + 1], al[mt], bb[2], bb[3]);
                }
                ldsm_x4(sA + G_BL + offB, bb);
#pragma unroll
                for (int mt = 0; mt < 2; mt++) {
                    mma_bf16(acc[mt][nt2 * 2], ah[mt], bb[0], bb[1]);
                    mma_bf16(acc[mt][nt2 * 2 + 1], ah[mt], bb[2], bb[3]);
                }
            }
        }
    }

#pragma unroll
    for (int mt = 0; mt < 2; mt++) {
        int r0 = m0 + wm + mt * 16 + (lane >> 2);
#pragma unroll
        for (int nt = 0; nt < 8; nt++) {
            int col = wn + nt * 8 + (lane & 3) * 2;
            if (r0 < M)
                *reinterpret_cast<float2*>(&C[(size_t)r0 * CC + col]) =
                    make_float2(acc[mt][nt][0], acc[mt][nt][1]);
            if (r0 + 8 < M)
                *reinterpret_cast<float2*>(&C[(size_t)(r0 + 8) * CC + col]) =
                    make_float2(acc[mt][nt][2], acc[mt][nt][3]);
        }
    }
}

// ================= GEMM with pre-split bf16 A (layer 2) =================

__global__ void __launch_bounds__(256, 2) gemm_mma_pre_kernel(
    const __nv_bfloat16* __restrict__ AHi, const __nv_bfloat16* __restrict__ ALo,
    const __nv_bfloat16* __restrict__ WTh, const __nv_bfloat16* __restrict__ WTl,
    float* __restrict__ C, int M) {
    extern __shared__ char smem[];
    uint32_t sA = smem_u32(smem);
    int tid = threadIdx.x;
    int lane = tid & 31, wid = tid >> 5;
    int wm = (wid & 3) * 32;
    int wn = (wid >> 2) * 64;
    int m0 = blockIdx.x * 128;

    float acc[2][8][4];
#pragma unroll
    for (int mt = 0; mt < 2; mt++)
#pragma unroll
        for (int nt = 0; nt < 8; nt++)
#pragma unroll
            for (int j = 0; j < 4; j++) acc[mt][nt][j] = 0.f;

    const uint4* AHv = (const uint4*)AHi;
    const uint4* ALv = (const uint4*)ALo;
    const uint4* BHv = (const uint4*)WTh;
    const uint4* BLv = (const uint4*)WTl;
    const uint4 Z = make_uint4(0, 0, 0, 0);

    // prefetch chunk-0 A (hi+lo)
    uint4 ahR[4], alR[4];
#pragma unroll
    for (int i = 0; i < 4; i++) {
        int g = tid + i * 256;
        int r = g >> 3, u = g & 7;
        int gm = m0 + r;
        ahR[i] = Z; alR[i] = Z;
        if (gm < M) {
            int gi = gm * 16 + u;
            ahR[i] = AHv[gi];
            alR[i] = ALv[gi];
        }
    }

    for (int c = 0; c < 2; c++) {
        if (c) __syncthreads();
#pragma unroll
        for (int i = 0; i < 4; i++) {
            int g = tid + i * 256;
            int r = g >> 3, u = g & 7;
            uint32_t off = SWZ128((uint32_t)(r * 128 + u * 16));
            *reinterpret_cast<uint4*>(smem + G_AH + off) = ahR[i];
            *reinterpret_cast<uint4*>(smem + G_AL + off) = alR[i];
        }
#pragma unroll
        for (int i = 0; i < 4; i++) {
            int g = tid + i * 256;
            int n = g >> 3;
            int u = g & 7;
            uint32_t off = SWZ128((uint32_t)(n * 128 + u * 16));
            int gi = n * 16 + c * 8 + u;
            *reinterpret_cast<uint4*>(smem + G_BH + off) = BHv[gi];
            *reinterpret_cast<uint4*>(smem + G_BL + off) = BLv[gi];
        }
        __syncthreads();

        if (c == 0) {
#pragma unroll
            for (int i = 0; i < 4; i++) {
                int g = tid + i * 256;
                int r = g >> 3, u = g & 7;
                int gm = m0 + r;
                ahR[i] = Z; alR[i] = Z;
                if (gm < M) {
                    int gi = gm * 16 + 8 + u;
                    ahR[i] = AHv[gi];
                    alR[i] = ALv[gi];
                }
            }
        }

#pragma unroll
        for (int ks = 0; ks < 4; ks++) {
            int kb = ks * 32;
            uint32_t ah[2][4], al[2][4];
#pragma unroll
            for (int mt = 0; mt < 2; mt++) {
                uint32_t offA = SWZ128((uint32_t)((wm + mt * 16 + (lane & 15)) * 128 +
                                                  kb + (lane & 16)));
                ldsm_x4(sA + G_AH + offA, ah[mt]);
                ldsm_x4(sA + G_AL + offA, al[mt]);
            }
#pragma unroll
            for (int nt2 = 0; nt2 < 4; nt2++) {
                uint32_t offB = SWZ128((uint32_t)((wn + nt2 * 16 + (lane & 7) +
                                                   ((lane & 16) >> 1)) * 128 +
                                                  kb + ((lane & 8) << 1)));
                uint32_t bb[4];
                ldsm_x4(sA + G_BH + offB, bb);
#pragma unroll
                for (int mt = 0; mt < 2; mt++) {
                    mma_bf16(acc[mt][nt2 * 2], ah[mt], bb[0], bb[1]);
                    mma_bf16(acc[mt][nt2 * 2 + 1], ah[mt], bb[2], bb[3]);
                    mma_bf16(acc[mt][nt2 * 2], al[mt], bb[0], bb[1]);
                    mma_bf16(acc[mt][nt2 * 2 + 1], al[mt], bb[2], bb[3]);
                }
                ldsm_x4(sA + G_BL + offB, bb);
#pragma unroll
                for (int mt = 0; mt < 2; mt++) {
                    mma_bf16(acc[mt][nt2 * 2], ah[mt], bb[0], bb[1]);
                    mma_bf16(acc[mt][nt2 * 2 + 1], ah[mt], bb[2], bb[3]);
                }
            }
        }
    }

#pragma unroll
    for (int mt = 0; mt < 2; mt++) {
        int r0 = m0 + wm + mt * 16 + (lane >> 2);
#pragma unroll
        for (int nt = 0; nt < 8; nt++) {
            int col = wn + nt * 8 + (lane & 3) * 2;
            if (r0 < M)
                *reinterpret_cast<float2*>(&C[(size_t)r0 * CC + col]) =
                    make_float2(acc[mt][nt][0], acc[mt][nt][1]);
            if (r0 + 8 < M)
                *reinterpret_cast<float2*>(&C[(size_t)(r0 + 8) * CC + col]) =
                    make_float2(acc[mt][nt][2], acc[mt][nt][3]);
        }
    }
}

// ================= dual-B GEMM with pre-split A =================
#define D_AH(c) ((uint32_t)(c) * 16384u)
#define D_AL(c) (32768u + (uint32_t)(c) * 16384u)
#define D_BH 65536u
#define D_BL 81920u
#define D_SMEM 98304

__global__ void __launch_bounds__(256, 2) gemm_dual_pre_kernel(
    const __nv_bfloat16* __restrict__ AHi, const __nv_bfloat16* __restrict__ ALo,
    const __nv_bfloat16* __restrict__ WTah, const __nv_bfloat16* __restrict__ WTal,
    const __nv_bfloat16* __restrict__ WTbh, const __nv_bfloat16* __restrict__ WTbl,
    float* __restrict__ C1, float* __restrict__ C2, int M) {
    extern __shared__ char smem[];
    uint32_t sA = smem_u32(smem);
    int tid = threadIdx.x;
    int lane = tid & 31, wid = tid >> 5;
    int wm = (wid & 3) * 32;
    int wn = (wid >> 2) * 64;
    int m0 = blockIdx.x * 128;

    const uint4* AHv = (const uint4*)AHi;
    const uint4* ALv = (const uint4*)ALo;
    const uint4 Z = make_uint4(0, 0, 0, 0);

    // ---- load full pre-split A (both chunks) ----
#pragma unroll
    for (int i = 0; i < 8; i++) {
        int g = tid + i * 256;        // uint4 id over 128 rows x 16
        int r = g >> 4;
        int u2 = g & 15;
        int chunk = u2 >> 3;
        int u = u2 & 7;
        int gm = m0 + r;
        uint4 vh = Z, vl = Z;
        if (gm < M) {
            int gi = gm * 16 + u2;
            vh = AHv[gi];
            vl = ALv[gi];
        }
        uint32_t off = SWZ128((uint32_t)(r * 128 + u * 16));
        *reinterpret_cast<uint4*>(smem + D_AH(chunk) + off) = vh;
        *reinterpret_cast<uint4*>(smem + D_AL(chunk) + off) = vl;
    }

    // B tile prefetch registers
    uint4 bhR[4], blR[4];
#pragma unroll
    for (int i = 0; i < 4; i++) {
        int g = tid + i * 256;
        int n = g >> 3, u = g & 7;
        int gi = n * 16 + u;
        bhR[i] = ((const uint4*)WTah)[gi];
        blR[i] = ((const uint4*)WTal)[gi];
    }

    for (int which = 0; which < 2; which++) {
        float* C = (which == 0) ? C1 : C2;

        float acc[2][8][4];
#pragma unroll
        for (int mt = 0; mt < 2; mt++)
#pragma unroll
            for (int nt = 0; nt < 8; nt++)
#pragma unroll
                for (int j = 0; j < 4; j++) acc[mt][nt][j] = 0.f;

        for (int c = 0; c < 2; c++) {
            int p = which * 2 + c;
            if (p) __syncthreads();
#pragma unroll
            for (int i = 0; i < 4; i++) {
                int g = tid + i * 256;
                int n = g >> 3, u = g & 7;
                uint32_t offb = SWZ128((uint32_t)(n * 128 + u * 16));
                *reinterpret_cast<uint4*>(smem + D_BH + offb) = bhR[i];
                *reinterpret_cast<uint4*>(smem + D_BL + offb) = blR[i];
            }
            __syncthreads();
            if (p < 3) {
                int np = p + 1;
                const uint4* H = (np < 2) ? (const uint4*)WTah : (const uint4*)WTbh;
                const uint4* L = (np < 2) ? (const uint4*)WTal : (const uint4*)WTbl;
                int nc = np & 1;
#pragma unroll
                for (int i = 0; i < 4; i++) {
                    int g = tid + i * 256;
                    int n = g >> 3, u = g & 7;
                    int gi = n * 16 + nc * 8 + u;
                    bhR[i] = H[gi];
                    blR[i] = L[gi];
                }
            }

#pragma unroll
            for (int ks = 0; ks < 4; ks++) {
                int kb = ks * 32;
                uint32_t ah[2][4], al[2][4];
#pragma unroll
                for (int mt = 0; mt < 2; mt++) {
                    uint32_t offA = SWZ128((uint32_t)((wm + mt * 16 + (lane & 15)) * 128 +
                                                      kb + (lane & 16)));
                    ldsm_x4(sA + D_AH(c) + offA, ah[mt]);
                    ldsm_x4(sA + D_AL(c) + offA, al[mt]);
                }
#pragma unroll
                for (int nt2 = 0; nt2 < 4; nt2++) {
                    uint32_t offB = SWZ128((uint32_t)((wn + nt2 * 16 + (lane & 7) +
                                                       ((lane & 16) >> 1)) * 128 +
                                                      kb + ((lane & 8) << 1)));
                    uint32_t bb[4];
                    ldsm_x4(sA + D_BH + offB, bb);
#pragma unroll
                    for (int mt = 0; mt < 2; mt++) {
                        mma_bf16(acc[mt][nt2 * 2], ah[mt], bb[0], bb[1]);
                        mma_bf16(acc[mt][nt2 * 2 + 1], ah[mt], bb[2], bb[3]);
                        mma_bf16(acc[mt][nt2 * 2], al[mt], bb[0], bb[1]);
                        mma_bf16(acc[mt][nt2 * 2 + 1], al[mt], bb[2], bb[3]);
                    }
                    ldsm_x4(sA + D_BL + offB, bb);
#pragma unroll
                    for (int mt = 0; mt < 2; mt++) {
                        mma_bf16(acc[mt][nt2 * 2], ah[mt], bb[0], bb[1]);
                        mma_bf16(acc[mt][nt2 * 2 + 1], ah[mt], bb[2], bb[3]);
                    }
                }
            }
        }

#pragma unroll
        for (int mt = 0; mt < 2; mt++) {
            int r0 = m0 + wm + mt * 16 + (lane >> 2);
#pragma unroll
            for (int nt = 0; nt < 8; nt++) {
                int col = wn + nt * 8 + (lane & 3) * 2;
                if (r0 < M)
                    *reinterpret_cast<float2*>(&C[(size_t)r0 * CC + col]) =
                        make_float2(acc[mt][nt][0], acc[mt][nt][1]);
                if (r0 + 8 < M)
                    *reinterpret_cast<float2*>(&C[(size_t)(r0 + 8) * CC + col]) =
                        make_float2(acc[mt][nt][2], acc[mt][nt][3]);
            }
        }
    }
}

// ================= pair stage =================

__global__ void __launch_bounds__(256) pair_kernel(
    const float* __restrict__ Z1, const float* __restrict__ Z2,
    const int* __restrict__ src, const int* __restrict__ dst,
    const float* __restrict__ bm1, const float* __restrict__ Wm2,
    const float* __restrict__ bm2,
    float* __restrict__ out, int P) {
    int gw = (blockIdx.x * blockDim.x + threadIdx.x) >> 5;
    if (gw >= P) return;
    int lane = threadIdx.x & 31;
    int s = __ldg(&src[gw]);
    int d = __ldg(&dst[gw]);
    float4 a = *reinterpret_cast<const float4*>(&Z1[(size_t)s * CC + lane * 4]);
    float4 b = *reinterpret_cast<const float4*>(&Z2[(size_t)d * CC + lane * 4]);
    float4 bb = __ldg(reinterpret_cast<const float4*>(&bm1[lane * 4]));
    float4 w = __ldg(reinterpret_cast<const float4*>(&Wm2[lane * 4]));
    float sum = fmaxf(a.x + b.x + bb.x, 0.f) * w.x
              + fmaxf(a.y + b.y + bb.y, 0.f) * w.y
              + fmaxf(a.z + b.z + bb.z, 0.f) * w.z
              + fmaxf(a.w + b.w + bb.w, 0.f) * w.w;
#pragma unroll
    for (int o = 16; o > 0; o >>= 1) sum += __shfl_xor_sync(0xFFFFFFFFu, sum, o);
    if (lane == 0) out[gw] = sum + __ldg(&bm2[0]);
}

// ================= launch =================

extern "C" void kernel_launch(void* const* d_in, const int* in_sizes, int n_in,
                              void* d_out, int out_size) {
    const float* x = (const float*)d_in[0];
    const int* edge_index = (const int*)d_in[1];
    const int* edge_pairs = (const int*)d_in[2];
    const float* W1 = (const float*)d_in[3];
    const float* b1 = (const float*)d_in[4];
    const float* W2 = (const float*)d_in[5];
    const float* b2 = (const float*)d_in[6];
    const float* Wm1 = (const float*)d_in[7];
    const float* bm1 = (const float*)d_in[8];
    const float* Wm2 = (const float*)d_in[9];
    const float* bm2 = (const float*)d_in[10];
    float* out = (float*)d_out;

    int N = in_sizes[0] / CC;
    int E = in_sizes[1] / 2;
    int P = in_sizes[2] / 2;
    const int* row = edge_index;
    const int* col = edge_index + E;
    const int* src = edge_pairs;
    const int* dst = edge_pairs + P;

    float *d_dinv, *d_t, *d_z1, *d_z2;
    __nv_bfloat16 *d_thi, *d_tlo;
    int *d_cnt, *d_off, *d_cur, *d_bsum, *d_csr;
    __nv_bfloat16* d_wt;
    cudaGetSymbolAddress((void**)&d_dinv, g_deg);
    cudaGetSymbolAddress((void**)&d_t, g_t);
    cudaGetSymbolAddress((void**)&d_thi, g_thi);
    cudaGetSymbolAddress((void**)&d_tlo, g_tlo);
    cudaGetSymbolAddress((void**)&d_z1, g_z1);
    cudaGetSymbolAddress((void**)&d_z2, g_z2);
    cudaGetSymbolAddress((void**)&d_cnt, g_cnt);
    cudaGetSymbolAddress((void**)&d_off, g_off);
    cudaGetSymbolAddress((void**)&d_cur, g_cur);
    cudaGetSymbolAddress((void**)&d_bsum, g_bsum);
    cudaGetSymbolAddress((void**)&d_csr, g_csr);
    cudaGetSymbolAddress((void**)&d_wt, g_wt);
    __nv_bfloat16* wt1h = d_wt + 0 * 32768;
    __nv_bfloat16* wt1l = wt1h + 16384;
    __nv_bfloat16* wt2h = d_wt + 1 * 32768;
    __nv_bfloat16* wt2l = wt2h + 16384;
    __nv_bfloat16* wtah = d_wt + 2 * 32768;
    __nv_bfloat16* wtal = wtah + 16384;
    __nv_bfloat16* wtbh = d_wt + 3 * 32768;
    __nv_bfloat16* wtbl = wtbh + 16384;

    cudaFuncSetAttribute(gemm_mma_kernel, cudaFuncAttributeMaxDynamicSharedMemorySize, G_SMEM);
    cudaFuncSetAttribute(gemm_mma_pre_kernel, cudaFuncAttributeMaxDynamicSharedMemorySize, G_SMEM);
    cudaFuncSetAttribute(gemm_dual_pre_kernel, cudaFuncAttributeMaxDynamicSharedMemorySize, D_SMEM);

    // side stream + fork/join events, created once on the (non-captured)
    // correctness call; only event record/wait happens during capture.
    static cudaStream_t s2 = nullptr;
    static cudaEvent_t evFork = nullptr, evJoin = nullptr;
    if (s2 == nullptr) {
        cudaStreamCreateWithFlags(&s2, cudaStreamNonBlocking);
        cudaEventCreateWithFlags(&evFork, cudaEventDisableTiming);
        cudaEventCreateWithFlags(&evJoin, cudaEventDisableTiming);
    }

    int nScanBlocks = (N + SCAN_T - 1) / SCAN_T;
    int gemmGrid = (N + 127) / 128;
    int aggGrid = (N + 7) / 8;

    // main: weight prep (layer-1 GEMM depends on it)
    wt_prep_all_kernel<<<256, 256>>>(W1, W2, Wm1, d_wt);

    // fork: CSR build chain on s2, concurrent with layer-1 GEMM on main
    cudaEventRecord(evFork, 0);
    cudaStreamWaitEvent(s2, evFork, 0);
    zero_cnt_kernel<<<(N + 255) / 256, 256, 0, s2>>>(d_cnt, N);
    hist_kernel<<<(E + 255) / 256, 256, 0, s2>>>(d_cnt, col, E);
    scan1_kernel<<<nScanBlocks, SCAN_T, 0, s2>>>(d_cnt, d_off, d_bsum, d_dinv, N);
    scan2_kernel<<<1, 256, 0, s2>>>(d_bsum, nScanBlocks);
    scan3_kernel<<<nScanBlocks, SCAN_T, 0, s2>>>(d_off, d_cur, d_bsum, N);
    fill_kernel<<<(E + 255) / 256, 256, 0, s2>>>(d_cur, d_csr, row, col, E);
    cudaEventRecord(evJoin, s2);

    // main: layer-1 GEMM (overlaps CSR build)  x @ W1 -> t
    gemm_mma_kernel<<<gemmGrid, 256, G_SMEM>>>(x, wt1h, wt1l, d_t, N);

    // join: aggregation needs both CSR and t
    cudaStreamWaitEvent(0, evJoin, 0);
    // agg1: h1 = relu(agg(t) + b1), written pre-split bf16 hi/lo
    agg_gather_split_kernel<<<aggGrid, 256>>>(d_t, d_thi, d_tlo, d_csr, d_off, d_cnt,
                                              d_dinv, b1, 1, N);

    // layer 2 GEMM: h1(pre-split) @ W2 -> t
    gemm_mma_pre_kernel<<<gemmGrid, 256, G_SMEM>>>(d_thi, d_tlo, wt2h, wt2l, d_t, N);

    // agg2: h2 = agg(t) + b2, pre-split
    agg_gather_split_kernel<<<aggGrid, 256>>>(d_t, d_thi, d_tlo, d_csr, d_off, d_cnt,
                                              d_dinv, b2, 0, N);

    // MLP projections: h2(pre-split) @ Wm_top -> Z1, @ Wm_bot -> Z2
    gemm_dual_pre_kernel<<<gemmGrid, 256, D_SMEM>>>(d_thi, d_tlo, wtah, wtal, wtbh, wtbl,
                                                    d_z1, d_z2, N);

    // pair stage
    pair_kernel<<<(P + 7) / 8, 256>>>(d_z1, d_z2, src, dst, bm1, Wm2, bm2, out, P);
}